// round 3
// baseline (speedup 1.0000x reference)
#include <cuda_runtime.h>

#define NN   50000
#define HIDD 64
#define EE   800000
#define EPN  100000
#define BNEPS 1e-5f
#define SB   ((NN + 255) / 256)   // 196 scan blocks

typedef unsigned long long ull;

// ---- scratch (static device globals; no allocation) ----
__device__ float g_x[NN * HIDD];
__device__ float g_h[NN * HIDD];
__device__ float g_agg[NN * HIDD];
__device__ float g_dis[NN];
__device__ int   g_deg[NN];
__device__ int   g_start[NN + 1];
__device__ int   g_cursor[NN];
__device__ int   g_bsum[SB];
__device__ int2  g_csr[EE];          // {src_row, bitcast(norm)}
__device__ float g_stats[2 * HIDD];  // [sum(64), sumsq(64)]

// ---- packed f32x2 helpers (Blackwell) ----
__device__ __forceinline__ ull pk2(float lo, float hi) {
    ull r; asm("mov.b64 %0, {%1, %2};" : "=l"(r) : "f"(lo), "f"(hi)); return r;
}
__device__ __forceinline__ void upk2(float& lo, float& hi, ull v) {
    asm("mov.b64 {%0, %1}, %2;" : "=f"(lo), "=f"(hi) : "l"(v));
}
__device__ __forceinline__ ull ffma2(ull a, ull b, ull c) {
    ull d; asm("fma.rn.f32x2 %0, %1, %2, %3;" : "=l"(d) : "l"(a), "l"(b), "l"(c)); return d;
}

// -------------------- degree --------------------

__global__ void zero_deg_k() {
    int i = blockIdx.x * blockDim.x + threadIdx.x;
    if (i < NN) g_deg[i] = 0;
}

__global__ void degree_k(const int* __restrict__ ei) {
    int e = blockIdx.x * blockDim.x + threadIdx.x;
    if (e < EE) atomicAdd(&g_deg[ei[EE + e]], 1);
}

// -------------------- 3-phase chip-wide exclusive scan of g_deg ------------

__global__ __launch_bounds__(256) void scan1_k() {
    __shared__ int sm[256];
    int t = threadIdx.x;
    int i = blockIdx.x * 256 + t;
    int v = 0;
    if (i < NN) {
        v = g_deg[i];
        g_dis[i] = rsqrtf((float)(v + 1));   // +1 self loop; always > 0
    }
    sm[t] = v;
    __syncthreads();
#pragma unroll
    for (int off = 128; off > 0; off >>= 1) {
        if (t < off) sm[t] += sm[t + off];
        __syncthreads();
    }
    if (t == 0) g_bsum[blockIdx.x] = sm[0];
}

__global__ __launch_bounds__(256) void scan2_k() {
    __shared__ int sm[256];
    int t = threadIdx.x;
    int v = (t < SB) ? g_bsum[t] : 0;
    sm[t] = v;
    __syncthreads();
#pragma unroll
    for (int off = 1; off < 256; off <<= 1) {
        int u = (t >= off) ? sm[t - off] : 0;
        __syncthreads();
        sm[t] += u;
        __syncthreads();
    }
    if (t < SB) g_bsum[t] = sm[t] - v;          // exclusive base per block
    if (t == SB - 1) g_start[NN] = sm[t];       // total
}

__global__ __launch_bounds__(256) void scan3_k() {
    __shared__ int sm[256];
    int t = threadIdx.x;
    int i = blockIdx.x * 256 + t;
    int v = (i < NN) ? g_deg[i] : 0;
    sm[t] = v;
    __syncthreads();
#pragma unroll
    for (int off = 1; off < 256; off <<= 1) {
        int u = (t >= off) ? sm[t - off] : 0;
        __syncthreads();
        sm[t] += u;
        __syncthreads();
    }
    if (i < NN) {
        int pos = g_bsum[blockIdx.x] + sm[t] - v;
        g_start[i]  = pos;
        g_cursor[i] = pos;
    }
}

__global__ void csr_build_k(const int* __restrict__ ei) {
    int e = blockIdx.x * blockDim.x + threadIdx.x;
    if (e >= EE) return;
    int r = ei[e];
    int c = ei[EE + e];
    int p = atomicAdd(&g_cursor[c], 1);
    float w = g_dis[r] * g_dis[c];
    g_csr[p] = make_int2(r, __float_as_int(w));
}

// -------------------- fused input projection: x = [id|n2v] @ W + b ----------
// K=128 in two 64-wide halves with packed-weight register reload.

__global__ __launch_bounds__(256) void proj_k(const float* __restrict__ id,
                                              const float* __restrict__ nv,
                                              const float* __restrict__ W,
                                              const float* __restrict__ bias,
                                              float* __restrict__ out) {
    __shared__ __align__(16) float xs[32 * 128];
    int tid  = threadIdx.x;
    int c    = tid & 63;
    int rq   = tid >> 6;
    int row0 = blockIdx.x * 32;

#pragma unroll
    for (int i = 0; i < 16; i++) {
        int idx = tid + i * 256;
        int row = row0 + (idx >> 7);
        int col = idx & 127;
        float v = 0.f;
        if (row < NN) v = (col < 64) ? id[row * 64 + col] : nv[row * 64 + col - 64];
        xs[idx] = v;
    }
    __syncthreads();

    const ull* xs2 = (const ull*)xs;
    ull acc[8][2];
#pragma unroll
    for (int r0 = 0; r0 < 8; r0++) { acc[r0][0] = 0ULL; acc[r0][1] = 0ULL; }

#pragma unroll
    for (int h = 0; h < 2; h++) {
        ull wp[32];
#pragma unroll
        for (int k2 = 0; k2 < 32; k2++)
            wp[k2] = pk2(W[(h * 64 + 2 * k2) * 64 + c], W[(h * 64 + 2 * k2 + 1) * 64 + c]);
#pragma unroll
        for (int r0 = 0; r0 < 8; r0++) {
            int r = rq * 8 + r0;
#pragma unroll
            for (int k2 = 0; k2 < 32; k2 += 2) {
                acc[r0][0] = ffma2(xs2[r * 64 + h * 32 + k2 + 0], wp[k2 + 0], acc[r0][0]);
                acc[r0][1] = ffma2(xs2[r * 64 + h * 32 + k2 + 1], wp[k2 + 1], acc[r0][1]);
            }
        }
    }

    float b = bias[c];
#pragma unroll
    for (int r0 = 0; r0 < 8; r0++) {
        int row = row0 + rq * 8 + r0;
        if (row < NN) {
            float l0, h0, l1, h1;
            upk2(l0, h0, acc[r0][0]);
            upk2(l1, h1, acc[r0][1]);
            out[row * 64 + c] = (l0 + h0) + (l1 + h1) + b;
        }
    }
}

// -------------------- packed 64x64 GEMM: out = A @ W --------------------

__global__ __launch_bounds__(256) void gemm64p_k(const float* __restrict__ A,
                                                 const float* __restrict__ W,
                                                 float* __restrict__ out) {
    __shared__ __align__(16) float xs[32 * 64];
    int tid  = threadIdx.x;
    int c    = tid & 63;
    int rq   = tid >> 6;
    int row0 = blockIdx.x * 32;

#pragma unroll
    for (int i = 0; i < 8; i++) {
        int idx = tid + i * 256;
        int row = row0 + (idx >> 6);
        xs[idx] = (row < NN) ? A[row * 64 + (idx & 63)] : 0.0f;
    }

    ull wp[32];
#pragma unroll
    for (int k2 = 0; k2 < 32; k2++)
        wp[k2] = pk2(W[(2 * k2) * 64 + c], W[(2 * k2 + 1) * 64 + c]);

    __syncthreads();
    const ull* xs2 = (const ull*)xs;

#pragma unroll
    for (int r0 = 0; r0 < 8; r0++) {
        int r   = rq * 8 + r0;
        int row = row0 + r;
        if (row >= NN) break;
        ull a0 = 0ULL, a1 = 0ULL, a2 = 0ULL, a3 = 0ULL;
#pragma unroll
        for (int k2 = 0; k2 < 32; k2 += 4) {
            a0 = ffma2(xs2[r * 32 + k2 + 0], wp[k2 + 0], a0);
            a1 = ffma2(xs2[r * 32 + k2 + 1], wp[k2 + 1], a1);
            a2 = ffma2(xs2[r * 32 + k2 + 2], wp[k2 + 2], a2);
            a3 = ffma2(xs2[r * 32 + k2 + 3], wp[k2 + 3], a3);
        }
        float l0, h0, l1, h1, l2, h2, l3, h3;
        upk2(l0, h0, a0); upk2(l1, h1, a1); upk2(l2, h2, a2); upk2(l3, h3, a3);
        out[row * 64 + c] = ((l0 + h0) + (l1 + h1)) + ((l2 + h2) + (l3 + h3));
    }
}

// ---- fused: x += relu(BN(agg)) during staging, then h = x @ W (layer 2) ----

__global__ __launch_bounds__(256) void gemmbn_k(const float* __restrict__ gamma,
                                                const float* __restrict__ beta,
                                                const float* __restrict__ W,
                                                float* __restrict__ out) {
    __shared__ __align__(16) float xs[32 * 64];
    int tid  = threadIdx.x;
    int c    = tid & 63;
    int rq   = tid >> 6;
    int row0 = blockIdx.x * 32;
    const float inv = 1.0f / (float)NN;

#pragma unroll
    for (int i = 0; i < 8; i++) {
        int idx = tid + i * 256;
        int row = row0 + (idx >> 6);
        int col = idx & 63;
        float v = 0.f;
        if (row < NN) {
            float mu  = g_stats[col] * inv;
            float var = g_stats[64 + col] * inv - mu * mu;
            float sc  = rsqrtf(var + BNEPS) * gamma[col];
            float bn  = (g_agg[row * 64 + col] - mu) * sc + beta[col];
            v = g_x[row * 64 + col] + fmaxf(bn, 0.f);
            g_x[row * 64 + col] = v;
        }
        xs[idx] = v;
    }

    ull wp[32];
#pragma unroll
    for (int k2 = 0; k2 < 32; k2++)
        wp[k2] = pk2(W[(2 * k2) * 64 + c], W[(2 * k2 + 1) * 64 + c]);

    __syncthreads();
    const ull* xs2 = (const ull*)xs;

#pragma unroll
    for (int r0 = 0; r0 < 8; r0++) {
        int r   = rq * 8 + r0;
        int row = row0 + r;
        if (row >= NN) break;
        ull a0 = 0ULL, a1 = 0ULL, a2 = 0ULL, a3 = 0ULL;
#pragma unroll
        for (int k2 = 0; k2 < 32; k2 += 4) {
            a0 = ffma2(xs2[r * 32 + k2 + 0], wp[k2 + 0], a0);
            a1 = ffma2(xs2[r * 32 + k2 + 1], wp[k2 + 1], a1);
            a2 = ffma2(xs2[r * 32 + k2 + 2], wp[k2 + 2], a2);
            a3 = ffma2(xs2[r * 32 + k2 + 3], wp[k2 + 3], a3);
        }
        float l0, h0, l1, h1, l2, h2, l3, h3;
        upk2(l0, h0, a0); upk2(l1, h1, a1); upk2(l2, h2, a2); upk2(l3, h3, a3);
        out[row * 64 + c] = ((l0 + h0) + (l1 + h1)) + ((l2 + h2) + (l3 + h3));
    }
}

// -------------------- gather aggregation (no float atomics) --------------------
// agg[n] = conv_b + dis[n]^2 * h[n] + sum_{edges into n} norm_e * h[src_e]
__global__ __launch_bounds__(256) void aggregate_k(const float* __restrict__ convb) {
    if (blockIdx.x == 0 && threadIdx.x < 128) g_stats[threadIdx.x] = 0.0f;

    int n    = blockIdx.x * 16 + (threadIdx.x >> 4);
    int lane = threadIdx.x & 15;
    if (n >= NN) return;

    const float4* h4 = (const float4*)g_h;
    float4 cb = ((const float4*)convb)[lane];
    float  d  = g_dis[n];
    float  w0 = d * d;
    float4 hv = h4[n * 16 + lane];

    float4 acc;
    acc.x = cb.x + w0 * hv.x;
    acc.y = cb.y + w0 * hv.y;
    acc.z = cb.z + w0 * hv.z;
    acc.w = cb.w + w0 * hv.w;

    int j = g_start[n];
    int e = g_start[n + 1];
    for (; j + 3 < e; j += 4) {
        int2  ra = g_csr[j + 0];
        int2  rb = g_csr[j + 1];
        int2  rc = g_csr[j + 2];
        int2  rd = g_csr[j + 3];
        float4 va = h4[ra.x * 16 + lane];
        float4 vb = h4[rb.x * 16 + lane];
        float4 vc = h4[rc.x * 16 + lane];
        float4 vd = h4[rd.x * 16 + lane];
        float wa = __int_as_float(ra.y);
        float wb = __int_as_float(rb.y);
        float wc = __int_as_float(rc.y);
        float wd = __int_as_float(rd.y);
        acc.x += wa * va.x; acc.y += wa * va.y; acc.z += wa * va.z; acc.w += wa * va.w;
        acc.x += wb * vb.x; acc.y += wb * vb.y; acc.z += wb * vb.z; acc.w += wb * vb.w;
        acc.x += wc * vc.x; acc.y += wc * vc.y; acc.z += wc * vc.z; acc.w += wc * vc.w;
        acc.x += wd * vd.x; acc.y += wd * vd.y; acc.z += wd * vd.z; acc.w += wd * vd.w;
    }
    for (; j < e; j++) {
        int2  ra = g_csr[j];
        float wa = __int_as_float(ra.y);
        float4 va = h4[ra.x * 16 + lane];
        acc.x += wa * va.x; acc.y += wa * va.y; acc.z += wa * va.z; acc.w += wa * va.w;
    }
    ((float4*)g_agg)[n * 16 + lane] = acc;
}

// -------------------- BatchNorm --------------------

__global__ __launch_bounds__(256) void bnstats_k() {
    int c = threadIdx.x & 63;
    int q = threadIdx.x >> 6;
    float s = 0.f, s2 = 0.f;
    for (int r = blockIdx.x * 4 + q; r < NN; r += gridDim.x * 4) {
        float v = g_agg[r * 64 + c];
        s += v;
        s2 += v * v;
    }
    __shared__ float sm[512];
    sm[threadIdx.x]       = s;
    sm[256 + threadIdx.x] = s2;
    __syncthreads();
    if (q == 0) {
        s  = sm[c] + sm[64 + c] + sm[128 + c] + sm[192 + c];
        s2 = sm[256 + c] + sm[256 + 64 + c] + sm[256 + 128 + c] + sm[256 + 192 + c];
        atomicAdd(&g_stats[c], s);
        atomicAdd(&g_stats[64 + c], s2);
    }
}

__global__ __launch_bounds__(256) void bnapply_k(const float* __restrict__ gamma,
                                                 const float* __restrict__ beta) {
    int idx = blockIdx.x * blockDim.x + threadIdx.x;
    if (idx >= NN * 16) return;
    int c0 = (idx & 15) * 4;
    const float inv = 1.0f / (float)NN;
    float4 a = ((const float4*)g_agg)[idx];
    float4 x = ((float4*)g_x)[idx];

    float mu, var, sc, v;
    mu = g_stats[c0 + 0] * inv; var = g_stats[64 + c0 + 0] * inv - mu * mu;
    sc = rsqrtf(var + BNEPS) * gamma[c0 + 0];
    v  = (a.x - mu) * sc + beta[c0 + 0]; x.x += fmaxf(v, 0.f);

    mu = g_stats[c0 + 1] * inv; var = g_stats[64 + c0 + 1] * inv - mu * mu;
    sc = rsqrtf(var + BNEPS) * gamma[c0 + 1];
    v  = (a.y - mu) * sc + beta[c0 + 1]; x.y += fmaxf(v, 0.f);

    mu = g_stats[c0 + 2] * inv; var = g_stats[64 + c0 + 2] * inv - mu * mu;
    sc = rsqrtf(var + BNEPS) * gamma[c0 + 2];
    v  = (a.z - mu) * sc + beta[c0 + 2]; x.z += fmaxf(v, 0.f);

    mu = g_stats[c0 + 3] * inv; var = g_stats[64 + c0 + 3] * inv - mu * mu;
    sc = rsqrtf(var + BNEPS) * gamma[c0 + 3];
    v  = (a.w - mu) * sc + beta[c0 + 3]; x.w += fmaxf(v, 0.f);

    ((float4*)g_x)[idx] = x;
}

// -------------------- decoder --------------------

__global__ __launch_bounds__(256) void decode_k(const int* __restrict__ pe,
                                                float* __restrict__ out) {
    int g    = blockIdx.x * 16 + (threadIdx.x >> 4);
    int lane = threadIdx.x & 15;
    if (g >= EPN) return;   // grid sized exactly; never taken (keeps shfl mask full)
    int a = pe[2 * g];
    int b = pe[2 * g + 1];
    const float4* z4 = (const float4*)g_x;
    float4 va = z4[a * 16 + lane];
    float4 vb = z4[b * 16 + lane];
    float d = va.x * vb.x + va.y * vb.y + va.z * vb.z + va.w * vb.w;
    d += __shfl_down_sync(0xffffffffu, d, 8, 16);
    d += __shfl_down_sync(0xffffffffu, d, 4, 16);
    d += __shfl_down_sync(0xffffffffu, d, 2, 16);
    d += __shfl_down_sync(0xffffffffu, d, 1, 16);
    if (lane == 0) out[g] = d;
}

// -------------------- launcher --------------------

extern "C" void kernel_launch(void* const* d_in, const int* in_sizes, int n_in,
                              void* d_out, int out_size) {
    const int*   edge_index = (const int*)d_in[0];
    const int*   pred_edge  = (const int*)d_in[1];
    const float* id_emb     = (const float*)d_in[2];
    const float* n2v_emb    = (const float*)d_in[3];
    const float* proj_w     = (const float*)d_in[4];
    const float* proj_b     = (const float*)d_in[5];
    const float* conv_w     = (const float*)d_in[6];
    const float* conv_b     = (const float*)d_in[7];
    const float* bn_gamma   = (const float*)d_in[8];
    const float* bn_beta    = (const float*)d_in[9];
    float*       out        = (float*)d_out;

    float *x_p, *h_p;
    cudaGetSymbolAddress((void**)&x_p, g_x);
    cudaGetSymbolAddress((void**)&h_p, g_h);

    const int GEMM_BLOCKS = (NN + 31) / 32;     // 1563
    const int EDGE_BLOCKS = (EE + 255) / 256;   // 3125
    const int NODE_BLOCKS = (NN + 255) / 256;   // 196
    const int AGG_BLOCKS  = (NN + 15) / 16;     // 3125
    const int APL_BLOCKS  = (NN * 16 + 255) / 256;
    const int DEC_BLOCKS  = (EPN + 15) / 16;    // 6250

    // graph structure (amortized over both layers)
    zero_deg_k<<<NODE_BLOCKS, 256>>>();
    degree_k<<<EDGE_BLOCKS, 256>>>(edge_index);
    scan1_k<<<SB, 256>>>();
    scan2_k<<<1, 256>>>();
    scan3_k<<<SB, 256>>>();
    csr_build_k<<<EDGE_BLOCKS, 256>>>(edge_index);

    // input projection: x = [id|n2v] @ proj_w + proj_b (fused, K=128)
    proj_k<<<GEMM_BLOCKS, 256>>>(id_emb, n2v_emb, proj_w, proj_b, x_p);

    // layer 1
    gemm64p_k<<<GEMM_BLOCKS, 256>>>(x_p, conv_w, h_p);
    aggregate_k<<<AGG_BLOCKS, 256>>>(conv_b);
    bnstats_k<<<256, 256>>>();

    // layer 2 (BN-apply of layer 1 fused into GEMM staging)
    gemmbn_k<<<GEMM_BLOCKS, 256>>>(bn_gamma, bn_beta, conv_w + 64 * 64, h_p);
    aggregate_k<<<AGG_BLOCKS, 256>>>(conv_b + 64);
    bnstats_k<<<256, 256>>>();
    bnapply_k<<<APL_BLOCKS, 256>>>(bn_gamma + 64, bn_beta + 64);

    decode_k<<<DEC_BLOCKS, 256>>>(pred_edge, out);
}